// round 10
// baseline (speedup 1.0000x reference)
#include <cuda_runtime.h>
#include <cstdint>

// image: [64, 3, 512, 512] fp32; mask [64,64] bool-as-int32 (rate ~0.5).
// out = where(mask8x8, -1.0f, image).
//
// R10: persistent grid-stride variant of the champion. Exactly 148*8 CTAs
// (one full wave at occ 8), each strides over the image. Removes CTA
// launch/drain churn for ~12k blocks and wave-quantization tail.
// Sector-predicated __ldcg loads, __stcs stores, UNROLL=4.

#define W4 128            // float4s per row (W=512)
#define UNROLL 4
#define NBLOCKS (148 * 8)

__global__ void __launch_bounds__(256) grid_crop_kernel(
    const float4* __restrict__ img,
    const int* __restrict__ sw,      // [64,64] bool-as-int32
    float4* __restrict__ out,
    int n4)
{
    const int stride = NBLOCKS * 256 * UNROLL;   // f4s per full-grid pass

    for (int base = blockIdx.x * (256 * UNROLL) + threadIdx.x;
         base < n4; base += stride)
    {
        int idx[UNROLL];
        int m[UNROLL];
        float4 v[UNROLL];

        #pragma unroll
        for (int k = 0; k < UNROLL; k++) {
            idx[k] = base + k * 256;
            int w4 = idx[k] & (W4 - 1);          // 0..127
            int h  = (idx[k] >> 7) & 511;        // 0..511
            m[k] = __ldg(&sw[((h >> 3) << 6) | (w4 >> 1)]);
        }

        #pragma unroll
        for (int k = 0; k < UNROLL; k++) {
            v[k] = make_float4(-1.0f, -1.0f, -1.0f, -1.0f);
            if (!m[k]) v[k] = __ldcg(&img[idx[k]]);
        }

        #pragma unroll
        for (int k = 0; k < UNROLL; k++) {
            __stcs(&out[idx[k]], v[k]);
        }
    }
}

extern "C" void kernel_launch(void* const* d_in, const int* in_sizes, int n_in,
                              void* d_out, int out_size)
{
    const void* p_img = d_in[0];
    const void* p_sw  = d_in[1];
    if (n_in >= 2 && in_sizes[0] < in_sizes[1]) {
        p_img = d_in[1];
        p_sw  = d_in[0];
    }

    const float4* img = (const float4*)p_img;
    const int* sw = (const int*)p_sw;
    float4* out = (float4*)d_out;

    int n4 = out_size / 4;                      // 12,582,912 (divisible by 1024)
    grid_crop_kernel<<<NBLOCKS, 256>>>(img, sw, out, n4);
}

// round 11
// speedup vs baseline: 1.0603x; 1.0603x over previous
#include <cuda_runtime.h>
#include <cstdint>

// image: [64, 3, 512, 512] fp32; mask [64,64] bool-as-int32 (rate ~0.5).
// out = where(mask8x8, -1.0f, image).
//
// Champion config (R9) with 512-thread blocks: identical per-thread code,
// half the CTAs, 8KB contiguous footprint per CTA for DRAM row locality.
// UNROLL=4, sector-predicated __ldcg loads, __stcs stores.

#define W4 128            // float4s per row (W=512)
#define UNROLL 4
#define TPB 512

__global__ void __launch_bounds__(TPB) grid_crop_kernel(
    const float4* __restrict__ img,
    const int* __restrict__ sw,      // [64,64] bool-as-int32
    float4* __restrict__ out)
{
    int base = blockIdx.x * (TPB * UNROLL) + threadIdx.x;

    int idx[UNROLL];
    int m[UNROLL];
    float4 v[UNROLL];

    // Mask lookups (L1-resident, broadcast across 8 adjacent threads).
    #pragma unroll
    for (int k = 0; k < UNROLL; k++) {
        idx[k] = base + k * TPB;
        int w4 = idx[k] & (W4 - 1);          // 0..127
        int h  = (idx[k] >> 7) & 511;        // 0..511
        m[k] = __ldg(&sw[((h >> 3) << 6) | (w4 >> 1)]);
    }

    // Predicated L2-only loads: fully-masked 128B lines never fetched.
    #pragma unroll
    for (int k = 0; k < UNROLL; k++) {
        v[k] = make_float4(-1.0f, -1.0f, -1.0f, -1.0f);
        if (!m[k]) v[k] = __ldcg(&img[idx[k]]);
    }

    // Evict-first streaming stores.
    #pragma unroll
    for (int k = 0; k < UNROLL; k++) {
        __stcs(&out[idx[k]], v[k]);
    }
}

extern "C" void kernel_launch(void* const* d_in, const int* in_sizes, int n_in,
                              void* d_out, int out_size)
{
    const void* p_img = d_in[0];
    const void* p_sw  = d_in[1];
    if (n_in >= 2 && in_sizes[0] < in_sizes[1]) {
        p_img = d_in[1];
        p_sw  = d_in[0];
    }

    const float4* img = (const float4*)p_img;
    const int* sw = (const int*)p_sw;
    float4* out = (float4*)d_out;

    int n4 = out_size / 4;                      // 12,582,912
    int blocks = n4 / (TPB * UNROLL);           // 6,144 exact
    grid_crop_kernel<<<blocks, TPB>>>(img, sw, out);
}